// round 4
// baseline (speedup 1.0000x reference)
#include <cuda_runtime.h>

#define CCH 32
#define HH 48
#define WW 48
#define DDD 48
#define PD 56
#define X1_CSTRIDE (48 * 48 * 48)    // 110592
#define X2P_CSTRIDE (56 * 56 * 56)   // 175616
#define RS 68                         // smem row stride in floats (272B, 16 mod 128)

typedef unsigned long long ull;

// Zero-padded copy of x2: layout (C, 56, 56, 56), d contiguous.
__device__ float g_x2p[CCH * PD * PD * PD];

__global__ void pad_kernel(const float* __restrict__ x2) {
    int idx = blockIdx.x * blockDim.x + threadIdx.x;
    const int total = CCH * PD * PD * PD;
    if (idx >= total) return;
    int dp = idx % PD;
    int t = idx / PD;
    int wp = t % PD;
    t /= PD;
    int hp = t % PD;
    int c = t / PD;
    int d = dp - 4, w = wp - 4, h = hp - 4;
    float v = 0.0f;
    if ((unsigned)h < (unsigned)HH && (unsigned)w < (unsigned)WW && (unsigned)d < (unsigned)DDD)
        v = x2[((c * HH + h) * WW + w) * DDD + d];
    g_x2p[idx] = v;
}

__device__ __forceinline__ ull pk2(float lo, float hi) {
    ull r;
    asm("mov.b64 %0, {%1, %2};" : "=l"(r) : "f"(lo), "f"(hi));
    return r;
}
__device__ __forceinline__ void fma2(ull& a, ull x, ull y) {
    asm("fma.rn.f32x2 %0, %1, %2, %0;" : "+l"(a) : "l"(x), "l"(y));
}
__device__ __forceinline__ void upk2(ull v, float& lo, float& hi) {
    asm("mov.b64 {%0, %1}, %2;" : "=f"(lo), "=f"(hi) : "l"(v));
}

// block = 96 threads: wl = t%16 (w row in tile), seg = t/16 (d segment of 8).
// CTA: (h, w-tile of 16, di, dj-pair {dj0, dj0+1}).
// Thread accumulates: acc1 = out(w0+wl, di, dj0, :) ; acc2 = out(w0+((wl+15)&15), di, dj0+1, :)
// Both consume x2 slab row wl (wl==0's acc2 uses halo row 16).
__global__ __launch_bounds__(96, 3)
void corr_kernel(const float* __restrict__ x1, float* __restrict__ out) {
    __shared__ float s1[16 * RS];   // x1 rows (48 fl used)
    __shared__ float s2[17 * RS];   // x2 rows (56 fl used)

    const int bx = blockIdx.x;          // 0..143
    const int h  = bx / 3;
    const int w0 = (bx % 3) * 16;
    const int g  = blockIdx.y;          // 0..44
    const int di  = g / 5;
    const int grp = g % 5;
    const int dj0 = grp * 2;
    const bool dual = (grp < 4);        // grp==4 -> single dj0=8

    const int t   = threadIdx.x;
    const int wl  = t & 15;
    const int seg = t >> 4;             // 0..5
    const int d0  = seg * 8;
    const int w_s2 = (wl + 15) & 15;

    const float* x1base = x1 + (h * WW + w0) * DDD;                       // contiguous 768 fl
    const float* x2base = g_x2p + ((h + di) * PD + (w0 + dj0)) * PD;      // contiguous region
    const int x2rows = min(17, PD - (w0 + dj0));
    const int x2f4   = x2rows * 14;

    ull acc1[4][9], acc2[4][9];
#pragma unroll
    for (int p = 0; p < 4; p++)
#pragma unroll
        for (int k = 0; k < 9; k++) { acc1[p][k] = 0ull; acc2[p][k] = 0ull; }

#pragma unroll 1
    for (int c = 0; c < CCH; c++) {
        // ---- fill (dense, coalesced) ----
        {
            const float4* g1 = (const float4*)(x1base + c * X1_CSTRIDE);
#pragma unroll
            for (int i = 0; i < 2; i++) {
                int idx = t + i * 96;               // 0..191
                int row = idx / 12, col = idx - row * 12;
                *(float4*)(s1 + row * RS + col * 4) = g1[idx];
            }
            const float4* g2 = (const float4*)(x2base + c * X2P_CSTRIDE);
#pragma unroll
            for (int i = 0; i < 3; i++) {
                int idx = t + i * 96;               // 0..287, need <238
                if (idx < 238) {
                    int row = idx / 14, col = idx - row * 14;
                    float4 v = make_float4(0.f, 0.f, 0.f, 0.f);
                    if (idx < x2f4) v = g2[idx];
                    *(float4*)(s2 + row * RS + col * 4) = v;
                }
            }
        }
        __syncthreads();

        // ---- compute ----
        {
            float4 a0 = *(const float4*)(s1 + wl * RS + d0);
            float4 a1 = *(const float4*)(s1 + wl * RS + d0 + 4);
            ull A1[4];
            A1[0] = pk2(a0.x, a0.y); A1[1] = pk2(a0.z, a0.w);
            A1[2] = pk2(a1.x, a1.y); A1[3] = pk2(a1.z, a1.w);
            float4 c0 = *(const float4*)(s1 + w_s2 * RS + d0);
            float4 c1 = *(const float4*)(s1 + w_s2 * RS + d0 + 4);
            ull A2[4];
            A2[0] = pk2(c0.x, c0.y); A2[1] = pk2(c0.z, c0.w);
            A2[2] = pk2(c1.x, c1.y); A2[3] = pk2(c1.z, c1.w);

            float4 b0 = *(const float4*)(s2 + wl * RS + d0);
            float4 b1 = *(const float4*)(s2 + wl * RS + d0 + 4);
            float4 b2 = *(const float4*)(s2 + wl * RS + d0 + 8);
            float4 b3 = *(const float4*)(s2 + wl * RS + d0 + 12);

            ull P[8], S[7];
            P[0] = pk2(b0.x, b0.y); P[1] = pk2(b0.z, b0.w);
            P[2] = pk2(b1.x, b1.y); P[3] = pk2(b1.z, b1.w);
            P[4] = pk2(b2.x, b2.y); P[5] = pk2(b2.z, b2.w);
            P[6] = pk2(b3.x, b3.y); P[7] = pk2(b3.z, b3.w);
            S[0] = pk2(b0.y, b0.z); S[1] = pk2(b0.w, b1.x);
            S[2] = pk2(b1.y, b1.z); S[3] = pk2(b1.w, b2.x);
            S[4] = pk2(b2.y, b2.z); S[5] = pk2(b2.w, b3.x);
            S[6] = pk2(b3.y, b3.z);

#pragma unroll
            for (int p = 0; p < 4; p++)
#pragma unroll
                for (int dk = 0; dk < 9; dk++) {
                    if (dk & 1) fma2(acc1[p][dk], A1[p], S[p + (dk >> 1)]);
                    else        fma2(acc1[p][dk], A1[p], P[p + (dk >> 1)]);
                }

            if (dual) {
                if (wl == 0) {   // halo row 16 for acc2 of the wrap thread
                    b0 = *(const float4*)(s2 + 16 * RS + d0);
                    b1 = *(const float4*)(s2 + 16 * RS + d0 + 4);
                    b2 = *(const float4*)(s2 + 16 * RS + d0 + 8);
                    b3 = *(const float4*)(s2 + 16 * RS + d0 + 12);
                    P[0] = pk2(b0.x, b0.y); P[1] = pk2(b0.z, b0.w);
                    P[2] = pk2(b1.x, b1.y); P[3] = pk2(b1.z, b1.w);
                    P[4] = pk2(b2.x, b2.y); P[5] = pk2(b2.z, b2.w);
                    P[6] = pk2(b3.x, b3.y); P[7] = pk2(b3.z, b3.w);
                    S[0] = pk2(b0.y, b0.z); S[1] = pk2(b0.w, b1.x);
                    S[2] = pk2(b1.y, b1.z); S[3] = pk2(b1.w, b2.x);
                    S[4] = pk2(b2.y, b2.z); S[5] = pk2(b2.w, b3.x);
                    S[6] = pk2(b3.y, b3.z);
                }
#pragma unroll
                for (int p = 0; p < 4; p++)
#pragma unroll
                    for (int dk = 0; dk < 9; dk++) {
                        if (dk & 1) fma2(acc2[p][dk], A2[p], S[p + (dk >> 1)]);
                        else        fma2(acc2[p][dk], A2[p], P[p + (dk >> 1)]);
                    }
            }
        }
        __syncthreads();
    }

    // ---- epilogue ----
    const float inv = 1.0f / 32.0f;
    {
        const size_t ob = (size_t)((h * WW + (w0 + wl)) * DDD + d0);
        const int o0 = (di * 9 + dj0) * 9;
#pragma unroll
        for (int dk = 0; dk < 9; dk++) {
            float* dst = out + (size_t)(o0 + dk) * X1_CSTRIDE + ob;
            float l0, h0, l1, h1;
            upk2(acc1[0][dk], l0, h0); upk2(acc1[1][dk], l1, h1);
            *(float4*)(dst + 0) = make_float4(l0 * inv, h0 * inv, l1 * inv, h1 * inv);
            upk2(acc1[2][dk], l0, h0); upk2(acc1[3][dk], l1, h1);
            *(float4*)(dst + 4) = make_float4(l0 * inv, h0 * inv, l1 * inv, h1 * inv);
        }
    }
    if (dual) {
        const size_t ob = (size_t)((h * WW + (w0 + w_s2)) * DDD + d0);
        const int o1 = (di * 9 + dj0 + 1) * 9;
#pragma unroll
        for (int dk = 0; dk < 9; dk++) {
            float* dst = out + (size_t)(o1 + dk) * X1_CSTRIDE + ob;
            float l0, h0, l1, h1;
            upk2(acc2[0][dk], l0, h0); upk2(acc2[1][dk], l1, h1);
            *(float4*)(dst + 0) = make_float4(l0 * inv, h0 * inv, l1 * inv, h1 * inv);
            upk2(acc2[2][dk], l0, h0); upk2(acc2[3][dk], l1, h1);
            *(float4*)(dst + 4) = make_float4(l0 * inv, h0 * inv, l1 * inv, h1 * inv);
        }
    }
}

extern "C" void kernel_launch(void* const* d_in, const int* in_sizes, int n_in,
                              void* d_out, int out_size) {
    const float* x1 = (const float*)d_in[0];
    const float* x2 = (const float*)d_in[1];
    float* out = (float*)d_out;

    const int total = CCH * PD * PD * PD;
    pad_kernel<<<(total + 255) / 256, 256>>>(x2);

    dim3 grid(144, 45);   // 48 h * 3 w-tiles, 9 di * 5 dj-groups
    corr_kernel<<<grid, 96>>>(x1, out);
}

// round 5
// speedup vs baseline: 1.0785x; 1.0785x over previous
#include <cuda_runtime.h>

#define CCH 32
#define HH 48
#define WW 48
#define DDD 48
#define PD 56
#define X1_CSTRIDE (48 * 48 * 48)    // 110592
#define X2P_CSTRIDE (56 * 56 * 56)   // 175616
#define RS1 52
#define RS2 60

typedef unsigned long long ull;

// Zero-padded copy of x2: layout (C, 56, 56, 56), d contiguous.
__device__ float g_x2p[CCH * PD * PD * PD];

__global__ void pad_kernel(const float* __restrict__ x2) {
    int idx = blockIdx.x * blockDim.x + threadIdx.x;
    const int total = CCH * PD * PD * PD;
    if (idx >= total) return;
    int dp = idx % PD;
    int t = idx / PD;
    int wp = t % PD;
    t /= PD;
    int hp = t % PD;
    int c = t / PD;
    int d = dp - 4, w = wp - 4, h = hp - 4;
    float v = 0.0f;
    if ((unsigned)h < (unsigned)HH && (unsigned)w < (unsigned)WW && (unsigned)d < (unsigned)DDD)
        v = x2[((c * HH + h) * WW + w) * DDD + d];
    g_x2p[idx] = v;
}

__device__ __forceinline__ ull pk2(float lo, float hi) {
    ull r;
    asm("mov.b64 %0, {%1, %2};" : "=l"(r) : "f"(lo), "f"(hi));
    return r;
}
__device__ __forceinline__ void fma2(ull& a, ull x, ull y) {
    asm("fma.rn.f32x2 %0, %1, %2, %0;" : "+l"(a) : "l"(x), "l"(y));
}
__device__ __forceinline__ void upk2(ull v, float& lo, float& hi) {
    asm("mov.b64 {%0, %1}, %2;" : "=f"(lo), "=f"(hi) : "l"(v));
}

// CTA = (h, w-tile of 4, di). 224 threads; active t<216: t = dj + 9*seg + 54*wl.
// Thread owns out(w0+wl, d0..d0+7, di, dj, all 9 dk). x1 window is dj-invariant
// -> 9-way LDS broadcast. x2 slab 12 rows x 56 d serves all 81 (dj,dk).
__global__ __launch_bounds__(224, 1)
void corr_kernel(const float* __restrict__ x1, float* __restrict__ out) {
    __shared__ float s1[2][4 * RS1];
    __shared__ float s2[2][12 * RS2];
    __shared__ float sout[4 * 48 * 9];   // [dj][wl][d] per dk slice

    const int bx = blockIdx.x;      // 0..575
    const int h  = bx / 12;
    const int w0 = (bx % 12) * 4;
    const int di = blockIdx.y;      // 0..8

    const int t = threadIdx.x;
    const bool act = (t < 216);
    const int dj  = t % 9;
    const int seg = (t / 9) % 6;
    const int wl  = t / 54;
    const int d0  = seg * 8;

    const float* x1base = x1 + (h * WW + w0) * DDD;                 // 192 fl contiguous
    const float* x2base = g_x2p + ((h + di) * PD + w0) * PD;        // 672 fl contiguous

    ull acc[4][9];
#pragma unroll
    for (int p = 0; p < 4; p++)
#pragma unroll
        for (int k = 0; k < 9; k++) acc[p][k] = 0ull;

    // ---- prologue fill (channel 0, buffer 0) ----
    {
        const float4* g1 = (const float4*)x1base;
        if (t < 48) {
            int row = t / 12, col = t - row * 12;
            *(float4*)&s1[0][row * RS1 + col * 4] = g1[t];
        }
        const float4* g2 = (const float4*)x2base;
        if (t < 168) {
            int row = t / 14, col = t - row * 14;
            *(float4*)&s2[0][row * RS2 + col * 4] = g2[t];
        }
    }

#pragma unroll 1
    for (int c = 0; c < CCH; c++) {
        __syncthreads();
        const int b = c & 1;
        // prefetch next channel into the other buffer
        if (c + 1 < CCH) {
            const float4* g1 = (const float4*)(x1base + (c + 1) * X1_CSTRIDE);
            if (t < 48) {
                int row = t / 12, col = t - row * 12;
                *(float4*)&s1[1 - b][row * RS1 + col * 4] = g1[t];
            }
            const float4* g2 = (const float4*)(x2base + (size_t)(c + 1) * X2P_CSTRIDE);
            if (t < 168) {
                int row = t / 14, col = t - row * 14;
                *(float4*)&s2[1 - b][row * RS2 + col * 4] = g2[t];
            }
        }

        if (act) {
            const float* S1p = &s1[b][wl * RS1 + d0];
            const float* S2p = &s2[b][(wl + dj) * RS2 + d0];

            float4 a0 = *(const float4*)(S1p);
            float4 a1 = *(const float4*)(S1p + 4);
            ull A[4];
            A[0] = pk2(a0.x, a0.y); A[1] = pk2(a0.z, a0.w);
            A[2] = pk2(a1.x, a1.y); A[3] = pk2(a1.z, a1.w);

            float4 b0 = *(const float4*)(S2p);
            float4 b1 = *(const float4*)(S2p + 4);
            float4 b2 = *(const float4*)(S2p + 8);
            float4 b3 = *(const float4*)(S2p + 12);

            ull P[8], S[7];
            P[0] = pk2(b0.x, b0.y); P[1] = pk2(b0.z, b0.w);
            P[2] = pk2(b1.x, b1.y); P[3] = pk2(b1.z, b1.w);
            P[4] = pk2(b2.x, b2.y); P[5] = pk2(b2.z, b2.w);
            P[6] = pk2(b3.x, b3.y); P[7] = pk2(b3.z, b3.w);
            S[0] = pk2(b0.y, b0.z); S[1] = pk2(b0.w, b1.x);
            S[2] = pk2(b1.y, b1.z); S[3] = pk2(b1.w, b2.x);
            S[4] = pk2(b2.y, b2.z); S[5] = pk2(b2.w, b3.x);
            S[6] = pk2(b3.y, b3.z);

#pragma unroll
            for (int p = 0; p < 4; p++)
#pragma unroll
                for (int dk = 0; dk < 9; dk++) {
                    if (dk & 1) fma2(acc[p][dk], A[p], S[p + (dk >> 1)]);
                    else        fma2(acc[p][dk], A[p], P[p + (dk >> 1)]);
                }
        }
    }

    // ---- epilogue: per-dk transpose through smem, then dense STG ----
    const float inv = 1.0f / 32.0f;
#pragma unroll 1
    for (int dk = 0; dk < 9; dk++) {
        __syncthreads();
        if (act) {
            const int base = (dj * 4 + wl) * 48 + d0;
            float l0, h0, l1, h1;
            upk2(acc[0][dk], l0, h0); upk2(acc[1][dk], l1, h1);
            *(float4*)&sout[base] = make_float4(l0 * inv, h0 * inv, l1 * inv, h1 * inv);
            upk2(acc[2][dk], l0, h0); upk2(acc[3][dk], l1, h1);
            *(float4*)&sout[base + 4] = make_float4(l0 * inv, h0 * inv, l1 * inv, h1 * inv);
        }
        __syncthreads();
        // copy 432 float4 (9 dj chunks, each 192 fl contiguous in gmem)
        if (act) {
#pragma unroll
            for (int rep = 0; rep < 2; rep++) {
                int i = t + rep * 216;             // 0..431
                int dj2 = i / 48, idx = i - dj2 * 48;
                int plane = (di * 9 + dj2) * 9 + dk;
                float* dst = out + (size_t)plane * X1_CSTRIDE + h * (WW * DDD) + w0 * DDD + idx * 4;
                *(float4*)dst = *(const float4*)&sout[i * 4];
            }
        }
    }
}

extern "C" void kernel_launch(void* const* d_in, const int* in_sizes, int n_in,
                              void* d_out, int out_size) {
    const float* x1 = (const float*)d_in[0];
    const float* x2 = (const float*)d_in[1];
    float* out = (float*)d_out;

    const int total = CCH * PD * PD * PD;
    pad_kernel<<<(total + 255) / 256, 256>>>(x2);

    dim3 grid(576, 9);   // (48 h * 12 w-tiles), 9 di
    corr_kernel<<<grid, 224>>>(x1, out);
}

// round 6
// speedup vs baseline: 2.0114x; 1.8650x over previous
#include <cuda_runtime.h>

#define CCH 32
#define HH 48
#define WW 48
#define DDD 48
#define PD 56
#define X1_CSTRIDE (48 * 48 * 48)    // 110592
#define X2P_CSTRIDE (56 * 56 * 56)   // 175616

typedef unsigned long long ull;

// Zero-padded copy of x2: layout (C, 56, 56, 56), d contiguous.
__device__ float g_x2p[CCH * PD * PD * PD];

__global__ void pad_kernel(const float* __restrict__ x2) {
    int idx = blockIdx.x * blockDim.x + threadIdx.x;
    const int total = CCH * PD * PD * PD;
    if (idx >= total) return;
    int dp = idx % PD;
    int t = idx / PD;
    int wp = t % PD;
    t /= PD;
    int hp = t % PD;
    int c = t / PD;
    int d = dp - 4, w = wp - 4, h = hp - 4;
    float v = 0.0f;
    if ((unsigned)h < (unsigned)HH && (unsigned)w < (unsigned)WW && (unsigned)d < (unsigned)DDD)
        v = x2[((c * HH + h) * WW + w) * DDD + d];
    g_x2p[idx] = v;
}

__device__ __forceinline__ ull pk2(float lo, float hi) {
    ull r;
    asm("mov.b64 %0, {%1, %2};" : "=l"(r) : "f"(lo), "f"(hi));
    return r;
}
__device__ __forceinline__ void fma2(ull& a, ull x, ull y) {
    asm("fma.rn.f32x2 %0, %1, %2, %0;" : "+l"(a) : "l"(x), "l"(y));
}
__device__ __forceinline__ void upk2(ull v, float& lo, float& hi) {
    asm("mov.b64 {%0, %1}, %2;" : "=f"(lo), "=f"(hi) : "l"(v));
}

// Diagonal-blocked, barrier-free kernel.
// CTA = (h, 8-row band of padded x2 rows s', di, dj-triple g).
// Thread t: chunk = t%12 -> d chunk D=4*chunk (dense 16B lane stride),
//           rl = t/12 -> s' = s0 + rl.
// Thread owns, for its fixed x2 row s', the 3 diagonal outputs
//   (w_j = s' - 3g - j, dj = 3g + j), j = 0..2  (predicated on 0<=w_j<48),
// each for all 9 dk and 4 d voxels. One 12-float x2 window feeds all 108 FMAs.
__global__ __launch_bounds__(96, 3)
void corr_kernel(const float* __restrict__ x1, float* __restrict__ out) {
    const int bx = blockIdx.x;          // 0..335
    const int h  = bx / 7;
    const int s0 = (bx % 7) * 8;
    const int by = blockIdx.y;          // 0..26
    const int di = by / 3;
    const int dj0 = (by % 3) * 3;

    const int t = threadIdx.x;          // 0..95
    const int chunk = t % 12;
    const int rl = t / 12;
    const int D = chunk * 4;
    const int sp = s0 + rl;             // padded w-row of x2, 0..55

    int wj[3];
    bool vj[3];
    const float* p1[3];
#pragma unroll
    for (int j = 0; j < 3; j++) {
        int w = sp - dj0 - j;
        wj[j] = w;
        vj[j] = ((unsigned)w < (unsigned)WW);
        int wc = min(WW - 1, max(0, w));
        p1[j] = x1 + (h * WW + wc) * DDD + D;
    }
    const float* p2 = g_x2p + ((h + di) * PD + sp) * PD + D;

    ull acc[3][2][9];
#pragma unroll
    for (int j = 0; j < 3; j++)
#pragma unroll
        for (int p = 0; p < 2; p++)
#pragma unroll
            for (int k = 0; k < 9; k++) acc[j][p][k] = 0ull;

    // software pipeline: loads for channel c+1 issued before computing c
    float4 a_c[3], b_c[3], a_n[3], b_n[3];
#pragma unroll
    for (int j = 0; j < 3; j++) a_c[j] = *(const float4*)(p1[j]);
    b_c[0] = *(const float4*)(p2);
    b_c[1] = *(const float4*)(p2 + 4);
    b_c[2] = *(const float4*)(p2 + 8);

#pragma unroll 1
    for (int c = 0; c < CCH; c++) {
        if (c + 1 < CCH) {
            const size_t o1 = (size_t)(c + 1) * X1_CSTRIDE;
            const size_t o2 = (size_t)(c + 1) * X2P_CSTRIDE;
#pragma unroll
            for (int j = 0; j < 3; j++) a_n[j] = *(const float4*)(p1[j] + o1);
            b_n[0] = *(const float4*)(p2 + o2);
            b_n[1] = *(const float4*)(p2 + o2 + 4);
            b_n[2] = *(const float4*)(p2 + o2 + 8);
        }

        ull A[3][2];
#pragma unroll
        for (int j = 0; j < 3; j++) {
            A[j][0] = pk2(a_c[j].x, a_c[j].y);
            A[j][1] = pk2(a_c[j].z, a_c[j].w);
        }
        ull P[6], S[5];
        P[0] = pk2(b_c[0].x, b_c[0].y); P[1] = pk2(b_c[0].z, b_c[0].w);
        P[2] = pk2(b_c[1].x, b_c[1].y); P[3] = pk2(b_c[1].z, b_c[1].w);
        P[4] = pk2(b_c[2].x, b_c[2].y); P[5] = pk2(b_c[2].z, b_c[2].w);
        S[0] = pk2(b_c[0].y, b_c[0].z); S[1] = pk2(b_c[0].w, b_c[1].x);
        S[2] = pk2(b_c[1].y, b_c[1].z); S[3] = pk2(b_c[1].w, b_c[2].x);
        S[4] = pk2(b_c[2].y, b_c[2].z);

#pragma unroll
        for (int j = 0; j < 3; j++)
#pragma unroll
            for (int p = 0; p < 2; p++)
#pragma unroll
                for (int dk = 0; dk < 9; dk++) {
                    if (dk & 1) fma2(acc[j][p][dk], A[j][p], S[p + (dk >> 1)]);
                    else        fma2(acc[j][p][dk], A[j][p], P[p + (dk >> 1)]);
                }

#pragma unroll
        for (int j = 0; j < 3; j++) a_c[j] = a_n[j];
        b_c[0] = b_n[0]; b_c[1] = b_n[1]; b_c[2] = b_n[2];
    }

    // epilogue: dense predicated stores (chunk fastest across warp)
    const float inv = 1.0f / 32.0f;
#pragma unroll
    for (int j = 0; j < 3; j++) {
        if (!vj[j]) continue;
        const size_t ob = (size_t)((h * WW + wj[j]) * DDD + D);
        const int pl0 = (di * 9 + dj0 + j) * 9;
#pragma unroll
        for (int dk = 0; dk < 9; dk++) {
            float l0, h0, l1, h1;
            upk2(acc[j][0][dk], l0, h0);
            upk2(acc[j][1][dk], l1, h1);
            *(float4*)(out + (size_t)(pl0 + dk) * X1_CSTRIDE + ob) =
                make_float4(l0 * inv, h0 * inv, l1 * inv, h1 * inv);
        }
    }
}

extern "C" void kernel_launch(void* const* d_in, const int* in_sizes, int n_in,
                              void* d_out, int out_size) {
    const float* x1 = (const float*)d_in[0];
    const float* x2 = (const float*)d_in[1];
    float* out = (float*)d_out;

    const int total = CCH * PD * PD * PD;
    pad_kernel<<<(total + 255) / 256, 256>>>(x2);

    dim3 grid(336, 27);   // (48 h * 7 s-bands), (9 di * 3 dj-triples)
    corr_kernel<<<grid, 96>>>(x1, out);
}

// round 9
// speedup vs baseline: 2.2235x; 1.1055x over previous
#include <cuda_runtime.h>

#define CCH 32
#define HH 48
#define WW 48
#define DDD 48
#define PDW 56
#define RD 64                         // padded d-row length (256B, line-aligned)
#define X1P_CSTRIDE (48 * 48 * RD)    // 147456
#define X2P_CSTRIDE (56 * 56 * RD)    // 200704
#define OUT_CSTRIDE (48 * 48 * 48)    // 110592

typedef unsigned long long ull;

// Padded copies, d-rows padded to 64 floats so every row is 128B-aligned.
__device__ float g_x1p[CCH * 48 * 48 * RD];          // (C, h, w, 64) ; d 0..47 valid
__device__ float g_x2p[CCH * PDW * PDW * RD];        // (C, h+4, w+4, 64) ; d' 0..55 = d-4

__global__ void pad1_kernel(const float* __restrict__ x1) {
    int idx = blockIdx.x * blockDim.x + threadIdx.x;
    const int total = CCH * 48 * 48 * RD;
    if (idx >= total) return;
    int d = idx % RD;
    int t = idx / RD;
    int w = t % 48; t /= 48;
    int h = t % 48;
    int c = t / 48;
    float v = 0.0f;
    if (d < DDD) v = x1[((c * HH + h) * WW + w) * DDD + d];
    g_x1p[idx] = v;
}

__global__ void pad2_kernel(const float* __restrict__ x2) {
    int idx = blockIdx.x * blockDim.x + threadIdx.x;
    const int total = CCH * PDW * PDW * RD;
    if (idx >= total) return;
    int dp = idx % RD;
    int t = idx / RD;
    int wp = t % PDW; t /= PDW;
    int hp = t % PDW;
    int c = t / PDW;
    int d = dp - 4, w = wp - 4, h = hp - 4;
    float v = 0.0f;
    if ((unsigned)h < (unsigned)HH && (unsigned)w < (unsigned)WW && (unsigned)d < (unsigned)DDD)
        v = x2[((c * HH + h) * WW + w) * DDD + d];
    g_x2p[idx] = v;
}

__device__ __forceinline__ void fma2(ull& a, ull x, ull y) {
    asm("fma.rn.f32x2 %0, %1, %2, %0;" : "+l"(a) : "l"(x), "l"(y));
}
__device__ __forceinline__ void upk2(ull v, float& lo, float& hi) {
    asm("mov.b64 {%0, %1}, %2;" : "=f"(lo), "=f"(hi) : "l"(v));
}
__device__ __forceinline__ ull shpair(ull a, ull b) {
    // (hi32(a), lo32(b)) as a packed f32x2 pair
    return (a >> 32) | (b << 32);
}

// Diagonal-blocked, barrier-free. CTA = (h, 8-row band of x2 rows, di, dj-triple).
// Thread t: chunk=t%12 -> d chunk D=4*chunk; rl=t/12 -> x2 row sp=s0+rl.
// Outputs (w_j = sp - dj0 - j, dj0+j), j=0..2, all 9 dk, 4 d voxels.
__global__ __launch_bounds__(96, 3)
void corr_kernel(float* __restrict__ out) {
    const int bx = blockIdx.x;          // 0..335
    const int h  = bx / 7;
    const int s0 = (bx % 7) * 8;
    const int by = blockIdx.y;          // 0..26
    const int di = by / 3;
    const int dj0 = (by % 3) * 3;

    const int t = threadIdx.x;          // 0..95
    const int chunk = t % 12;
    const int rl = t / 12;
    const int D = chunk * 4;
    const int sp = s0 + rl;             // padded w-row of x2, 0..55

    int wj[3];
    bool vj[3];
    const float* p1[3];
#pragma unroll
    for (int j = 0; j < 3; j++) {
        int w = sp - dj0 - j;
        wj[j] = w;
        vj[j] = ((unsigned)w < (unsigned)WW);
        int wc = min(WW - 1, max(0, w));
        p1[j] = g_x1p + (h * 48 + wc) * RD + D;
    }
    const float* p2 = g_x2p + ((h + di) * PDW + sp) * RD + D;

    ull acc[3][2][9];
#pragma unroll
    for (int j = 0; j < 3; j++)
#pragma unroll
        for (int p = 0; p < 2; p++)
#pragma unroll
            for (int k = 0; k < 9; k++) acc[j][p][k] = 0ull;

    ulonglong2 A0[3], A1[3];        // x1 windows (2 pairs each)
    ulonglong2 B0[3], B1[3];        // x2 window: 3 overlapping-free 16B loads = P[0..5]

#define LOADCH(Abuf, Bbuf, cc)                                                     \
    do {                                                                           \
        const size_t o1 = (size_t)(cc) * X1P_CSTRIDE;                              \
        const size_t o2 = (size_t)(cc) * X2P_CSTRIDE;                              \
        Abuf[0] = *(const ulonglong2*)(p1[0] + o1);                                \
        Abuf[1] = *(const ulonglong2*)(p1[1] + o1);                                \
        Abuf[2] = *(const ulonglong2*)(p1[2] + o1);                                \
        Bbuf[0] = *(const ulonglong2*)(p2 + o2);                                   \
        Bbuf[1] = *(const ulonglong2*)(p2 + o2 + 4);                               \
        Bbuf[2] = *(const ulonglong2*)(p2 + o2 + 8);                               \
    } while (0)

#define COMPUTECH(Abuf, Bbuf)                                                      \
    do {                                                                           \
        ull P[6];                                                                  \
        P[0] = Bbuf[0].x; P[1] = Bbuf[0].y;                                        \
        P[2] = Bbuf[1].x; P[3] = Bbuf[1].y;                                        \
        P[4] = Bbuf[2].x; P[5] = Bbuf[2].y;                                        \
        ull S[5];                                                                  \
        S[0] = shpair(P[0], P[1]); S[1] = shpair(P[1], P[2]);                      \
        S[2] = shpair(P[2], P[3]); S[3] = shpair(P[3], P[4]);                      \
        S[4] = shpair(P[4], P[5]);                                                 \
        _Pragma("unroll")                                                          \
        for (int j = 0; j < 3; j++) {                                              \
            const ull Aj0 = Abuf[j].x, Aj1 = Abuf[j].y;                            \
            _Pragma("unroll")                                                      \
            for (int dk = 0; dk < 9; dk++) {                                       \
                const int m = dk >> 1;                                             \
                if (dk & 1) {                                                      \
                    fma2(acc[j][0][dk], Aj0, S[m]);                                \
                    fma2(acc[j][1][dk], Aj1, S[m + 1]);                            \
                } else {                                                           \
                    fma2(acc[j][0][dk], Aj0, P[m]);                                \
                    fma2(acc[j][1][dk], Aj1, P[m + 1]);                            \
                }                                                                  \
            }                                                                      \
        }                                                                          \
    } while (0)

    LOADCH(A0, B0, 0);
#pragma unroll 1
    for (int c = 0; c < CCH; c += 2) {
        LOADCH(A1, B1, c + 1);
        COMPUTECH(A0, B0);
        if (c + 2 < CCH) LOADCH(A0, B0, c + 2);
        COMPUTECH(A1, B1);
    }

    // epilogue: dense predicated stores (chunk fastest across warp)
    const float inv = 1.0f / 32.0f;
#pragma unroll
    for (int j = 0; j < 3; j++) {
        if (!vj[j]) continue;
        const size_t ob = (size_t)((h * WW + wj[j]) * DDD + D);
        const int pl0 = (di * 9 + dj0 + j) * 9;
#pragma unroll
        for (int dk = 0; dk < 9; dk++) {
            float l0, h0, l1, h1;
            upk2(acc[j][0][dk], l0, h0);
            upk2(acc[j][1][dk], l1, h1);
            *(float4*)(out + (size_t)(pl0 + dk) * OUT_CSTRIDE + ob) =
                make_float4(l0 * inv, h0 * inv, l1 * inv, h1 * inv);
        }
    }
}

extern "C" void kernel_launch(void* const* d_in, const int* in_sizes, int n_in,
                              void* d_out, int out_size) {
    const float* x1 = (const float*)d_in[0];
    const float* x2 = (const float*)d_in[1];
    float* out = (float*)d_out;

    const int t1 = CCH * 48 * 48 * RD;
    pad1_kernel<<<(t1 + 255) / 256, 256>>>(x1);
    const int t2 = CCH * PDW * PDW * RD;
    pad2_kernel<<<(t2 + 255) / 256, 256>>>(x2);

    dim3 grid(336, 27);   // (48 h * 7 s-bands), (9 di * 3 dj-triples)
    corr_kernel<<<grid, 96>>>(out);
}

// round 10
// speedup vs baseline: 2.5122x; 1.1298x over previous
#include <cuda_runtime.h>

#define CCH 32
#define HH 48
#define WW 48
#define DDD 48
#define PDW 56
#define RD2 56                          // x2 scratch row length in floats (224B, packed)
#define X1_CSTRIDE (48 * 48 * 48)       // 110592
#define X2P_CSTRIDE (56 * 56 * RD2)     // 175616
#define OUT_CSTRIDE (48 * 48 * 48)      // 110592

typedef unsigned long long ull;

// Zero-padded x2 copy: (C, h+4, w+4, d'=d+4 in 56-float rows).
__device__ float g_x2p[CCH * PDW * PDW * RD2];

// float4-granular pad: d' chunk f4 covers d = f4*4-4 .. f4*4-1
//  f4==0  -> all d<0   -> zeros
//  f4==13 -> all d>=48 -> zeros
//  else   -> one aligned float4 from source at (f4-1)*4
__global__ void pad2_kernel(const float* __restrict__ x2) {
    int idx = blockIdx.x * blockDim.x + threadIdx.x;
    const int total = CCH * PDW * PDW * (RD2 / 4);
    if (idx >= total) return;
    int f4 = idx % (RD2 / 4);
    int t = idx / (RD2 / 4);
    int wp = t % PDW; t /= PDW;
    int hp = t % PDW;
    int c = t / PDW;
    int w = wp - 4, h = hp - 4;
    float4 v = make_float4(0.f, 0.f, 0.f, 0.f);
    if ((unsigned)h < (unsigned)HH && (unsigned)w < (unsigned)WW && f4 >= 1 && f4 <= 12)
        v = *(const float4*)(x2 + ((c * HH + h) * WW + w) * DDD + (f4 - 1) * 4);
    *(float4*)(g_x2p + (size_t)idx * 4) = v;
}

__device__ __forceinline__ void fma2(ull& a, ull x, ull y) {
    asm("fma.rn.f32x2 %0, %1, %2, %0;" : "+l"(a) : "l"(x), "l"(y));
}
__device__ __forceinline__ void upk2(ull v, float& lo, float& hi) {
    asm("mov.b64 {%0, %1}, %2;" : "=f"(lo), "=f"(hi) : "l"(v));
}
__device__ __forceinline__ ull shpair(ull a, ull b) {
    // (hi32(a), lo32(b)) as a packed f32x2 pair
    return (a >> 32) | (b << 32);
}

// Diagonal-blocked, barrier-free. CTA = (h, 8-row band of x2 rows, di, dj-triple).
// Thread t: chunk=t%12 -> d chunk D=4*chunk; rl=t/12 -> x2 row sp=s0+rl.
// Outputs (w_j = sp - dj0 - j, dj0+j), j=0..2, all 9 dk, 4 d voxels.
// x1 read in place (rows packed 192B -> warp-dense); x2 from packed scratch.
__global__ __launch_bounds__(96, 3)
void corr_kernel(const float* __restrict__ x1, float* __restrict__ out) {
    const int bx = blockIdx.x;          // 0..335
    const int h  = bx / 7;
    const int s0 = (bx % 7) * 8;
    const int by = blockIdx.y;          // 0..26
    const int di = by / 3;
    const int dj0 = (by % 3) * 3;

    const int t = threadIdx.x;          // 0..95
    const int chunk = t % 12;
    const int rl = t / 12;
    const int D = chunk * 4;
    const int sp = s0 + rl;             // padded w-row of x2, 0..55

    int wj[3];
    bool vj[3];
    const float* p1[3];
#pragma unroll
    for (int j = 0; j < 3; j++) {
        int w = sp - dj0 - j;
        wj[j] = w;
        vj[j] = ((unsigned)w < (unsigned)WW);
        int wc = min(WW - 1, max(0, w));
        p1[j] = x1 + (h * WW + wc) * DDD + D;
    }
    const float* p2 = g_x2p + ((h + di) * PDW + sp) * RD2 + D;   // window D..D+11 <= 56

    ull acc[3][2][9];
#pragma unroll
    for (int j = 0; j < 3; j++)
#pragma unroll
        for (int p = 0; p < 2; p++)
#pragma unroll
            for (int k = 0; k < 9; k++) acc[j][p][k] = 0ull;

    ulonglong2 A0[3], A1[3];
    ulonglong2 B0[3], B1[3];

#define LOADCH(Abuf, Bbuf, cc)                                                     \
    do {                                                                           \
        const size_t o1 = (size_t)(cc) * X1_CSTRIDE;                               \
        const size_t o2 = (size_t)(cc) * X2P_CSTRIDE;                              \
        Abuf[0] = *(const ulonglong2*)(p1[0] + o1);                                \
        Abuf[1] = *(const ulonglong2*)(p1[1] + o1);                                \
        Abuf[2] = *(const ulonglong2*)(p1[2] + o1);                                \
        Bbuf[0] = *(const ulonglong2*)(p2 + o2);                                   \
        Bbuf[1] = *(const ulonglong2*)(p2 + o2 + 4);                               \
        Bbuf[2] = *(const ulonglong2*)(p2 + o2 + 8);                               \
    } while (0)

#define COMPUTECH(Abuf, Bbuf)                                                      \
    do {                                                                           \
        ull P[6];                                                                  \
        P[0] = Bbuf[0].x; P[1] = Bbuf[0].y;                                        \
        P[2] = Bbuf[1].x; P[3] = Bbuf[1].y;                                        \
        P[4] = Bbuf[2].x; P[5] = Bbuf[2].y;                                        \
        ull S[5];                                                                  \
        S[0] = shpair(P[0], P[1]); S[1] = shpair(P[1], P[2]);                      \
        S[2] = shpair(P[2], P[3]); S[3] = shpair(P[3], P[4]);                      \
        S[4] = shpair(P[4], P[5]);                                                 \
        _Pragma("unroll")                                                          \
        for (int j = 0; j < 3; j++) {                                              \
            const ull Aj0 = Abuf[j].x, Aj1 = Abuf[j].y;                            \
            _Pragma("unroll")                                                      \
            for (int dk = 0; dk < 9; dk++) {                                       \
                const int m = dk >> 1;                                             \
                if (dk & 1) {                                                      \
                    fma2(acc[j][0][dk], Aj0, S[m]);                                \
                    fma2(acc[j][1][dk], Aj1, S[m + 1]);                            \
                } else {                                                           \
                    fma2(acc[j][0][dk], Aj0, P[m]);                                \
                    fma2(acc[j][1][dk], Aj1, P[m + 1]);                            \
                }                                                                  \
            }                                                                      \
        }                                                                          \
    } while (0)

    LOADCH(A0, B0, 0);
#pragma unroll 1
    for (int c = 0; c < CCH; c += 2) {
        LOADCH(A1, B1, c + 1);
        COMPUTECH(A0, B0);
        if (c + 2 < CCH) LOADCH(A0, B0, c + 2);
        COMPUTECH(A1, B1);
    }

    // epilogue: dense predicated stores (chunk fastest across warp)
    const float inv = 1.0f / 32.0f;
#pragma unroll
    for (int j = 0; j < 3; j++) {
        if (!vj[j]) continue;
        const size_t ob = (size_t)((h * WW + wj[j]) * DDD + D);
        const int pl0 = (di * 9 + dj0 + j) * 9;
#pragma unroll
        for (int dk = 0; dk < 9; dk++) {
            float l0, h0, l1, h1;
            upk2(acc[j][0][dk], l0, h0);
            upk2(acc[j][1][dk], l1, h1);
            *(float4*)(out + (size_t)(pl0 + dk) * OUT_CSTRIDE + ob) =
                make_float4(l0 * inv, h0 * inv, l1 * inv, h1 * inv);
        }
    }
}

extern "C" void kernel_launch(void* const* d_in, const int* in_sizes, int n_in,
                              void* d_out, int out_size) {
    const float* x1 = (const float*)d_in[0];
    const float* x2 = (const float*)d_in[1];
    float* out = (float*)d_out;

    const int t2 = CCH * PDW * PDW * (RD2 / 4);
    pad2_kernel<<<(t2 + 255) / 256, 256>>>(x2);

    dim3 grid(336, 27);   // (48 h * 7 s-bands), (9 di * 3 dj-triples)
    corr_kernel<<<grid, 96>>>(x1, out);
}

// round 11
// speedup vs baseline: 2.7107x; 1.0790x over previous
#include <cuda_runtime.h>

#define CCH 32
#define HH 48
#define WW 48
#define DDD 48
#define PDW 56
#define RD2 56                          // x2 scratch row length in floats (224B, packed)
#define X1_CSTRIDE (48 * 48 * 48)       // 110592
#define X2P_CSTRIDE (56 * 56 * RD2)     // 175616
#define OUT_CSTRIDE (48 * 48 * 48)      // 110592

typedef unsigned long long ull;

// Zero-padded x2 copy: (C, h+4, w+4, d'=d+4 in 56-float rows).
__device__ float g_x2p[CCH * PDW * PDW * RD2];

__global__ void pad2_kernel(const float* __restrict__ x2) {
    int idx = blockIdx.x * blockDim.x + threadIdx.x;
    const int total = CCH * PDW * PDW * (RD2 / 4);
    if (idx >= total) return;
    int f4 = idx % (RD2 / 4);
    int t = idx / (RD2 / 4);
    int wp = t % PDW; t /= PDW;
    int hp = t % PDW;
    int c = t / PDW;
    int w = wp - 4, h = hp - 4;
    float4 v = make_float4(0.f, 0.f, 0.f, 0.f);
    if ((unsigned)h < (unsigned)HH && (unsigned)w < (unsigned)WW && f4 >= 1 && f4 <= 12)
        v = *(const float4*)(x2 + ((c * HH + h) * WW + w) * DDD + (f4 - 1) * 4);
    *(float4*)(g_x2p + (size_t)idx * 4) = v;
}

__device__ __forceinline__ void fma2(ull& a, ull x, ull y) {
    asm("fma.rn.f32x2 %0, %1, %2, %0;" : "+l"(a) : "l"(x), "l"(y));
}
__device__ __forceinline__ void upk2(ull v, float& lo, float& hi) {
    asm("mov.b64 {%0, %1}, %2;" : "=f"(lo), "=f"(hi) : "l"(v));
}
// (hi32(a), lo32(b)) as packed f32x2 — register-pair select, 2 MOVs max.
__device__ __forceinline__ ull selpair(ull a, ull b) {
    float alo, ahi, blo, bhi;
    upk2(a, alo, ahi);
    upk2(b, blo, bhi);
    ull r;
    asm("mov.b64 %0, {%1, %2};" : "=l"(r) : "f"(ahi), "f"(blo));
    return r;
}

// Diagonal-blocked, barrier-free. CTA = (h, 8-row band of x2 rows, di, dj-triple).
// Thread t: chunk=t%12 -> d chunk D=4*chunk; rl=t/12 -> x2 row sp=s0+rl.
// Outputs (w_j = sp - dj0 - j, dj0+j), j=0..2, all 9 dk, 4 d voxels.
__global__ __launch_bounds__(96, 4)
void corr_kernel(const float* __restrict__ x1, float* __restrict__ out) {
    const int bx = blockIdx.x;          // 0..335
    const int h  = bx / 7;
    const int s0 = (bx % 7) * 8;
    const int by = blockIdx.y;          // 0..26
    const int di = by / 3;
    const int dj0 = (by % 3) * 3;

    const int t = threadIdx.x;          // 0..95
    const int chunk = t % 12;
    const int rl = t / 12;
    const int D = chunk * 4;
    const int sp = s0 + rl;             // padded w-row of x2, 0..55

    int wj[3];
    bool vj[3];
    const float* p1[3];
#pragma unroll
    for (int j = 0; j < 3; j++) {
        int w = sp - dj0 - j;
        wj[j] = w;
        vj[j] = ((unsigned)w < (unsigned)WW);
        int wc = min(WW - 1, max(0, w));
        p1[j] = x1 + (h * WW + wc) * DDD + D;
    }
    const float* p2 = g_x2p + ((h + di) * PDW + sp) * RD2 + D;   // window D..D+11 <= 56

    ull acc[3][2][9];
#pragma unroll
    for (int j = 0; j < 3; j++)
#pragma unroll
        for (int p = 0; p < 2; p++)
#pragma unroll
            for (int k = 0; k < 9; k++) acc[j][p][k] = 0ull;

    ulonglong2 A0[3], A1[3];
    ulonglong2 B0[3], B1[3];

// load current pointer positions, then advance pointers by one channel stride
#define LOADCH(Abuf, Bbuf)                                                         \
    do {                                                                           \
        Abuf[0] = *(const ulonglong2*)(p1[0]);                                     \
        Abuf[1] = *(const ulonglong2*)(p1[1]);                                     \
        Abuf[2] = *(const ulonglong2*)(p1[2]);                                     \
        Bbuf[0] = *(const ulonglong2*)(p2);                                        \
        Bbuf[1] = *(const ulonglong2*)(p2 + 4);                                    \
        Bbuf[2] = *(const ulonglong2*)(p2 + 8);                                    \
        p1[0] += X1_CSTRIDE; p1[1] += X1_CSTRIDE; p1[2] += X1_CSTRIDE;             \
        p2 += X2P_CSTRIDE;                                                         \
    } while (0)

#define COMPUTECH(Abuf, Bbuf)                                                      \
    do {                                                                           \
        ull P[6];                                                                  \
        P[0] = Bbuf[0].x; P[1] = Bbuf[0].y;                                        \
        P[2] = Bbuf[1].x; P[3] = Bbuf[1].y;                                        \
        P[4] = Bbuf[2].x; P[5] = Bbuf[2].y;                                        \
        ull S[5];                                                                  \
        S[0] = selpair(P[0], P[1]); S[1] = selpair(P[1], P[2]);                    \
        S[2] = selpair(P[2], P[3]); S[3] = selpair(P[3], P[4]);                    \
        S[4] = selpair(P[4], P[5]);                                                \
        _Pragma("unroll")                                                          \
        for (int j = 0; j < 3; j++) {                                              \
            const ull Aj0 = Abuf[j].x, Aj1 = Abuf[j].y;                            \
            _Pragma("unroll")                                                      \
            for (int dk = 0; dk < 9; dk++) {                                       \
                const int m = dk >> 1;                                             \
                if (dk & 1) {                                                      \
                    fma2(acc[j][0][dk], Aj0, S[m]);                                \
                    fma2(acc[j][1][dk], Aj1, S[m + 1]);                            \
                } else {                                                           \
                    fma2(acc[j][0][dk], Aj0, P[m]);                                \
                    fma2(acc[j][1][dk], Aj1, P[m + 1]);                            \
                }                                                                  \
            }                                                                      \
        }                                                                          \
    } while (0)

    LOADCH(A0, B0);
#pragma unroll 1
    for (int c = 0; c < CCH; c += 2) {
        LOADCH(A1, B1);
        COMPUTECH(A0, B0);
        if (c + 2 < CCH) LOADCH(A0, B0);
        COMPUTECH(A1, B1);
    }

    // epilogue: dense predicated stores (chunk fastest across warp)
    const float inv = 1.0f / 32.0f;
#pragma unroll
    for (int j = 0; j < 3; j++) {
        if (!vj[j]) continue;
        const size_t ob = (size_t)((h * WW + wj[j]) * DDD + D);
        const int pl0 = (di * 9 + dj0 + j) * 9;
#pragma unroll
        for (int dk = 0; dk < 9; dk++) {
            float l0, h0, l1, h1;
            upk2(acc[j][0][dk], l0, h0);
            upk2(acc[j][1][dk], l1, h1);
            *(float4*)(out + (size_t)(pl0 + dk) * OUT_CSTRIDE + ob) =
                make_float4(l0 * inv, h0 * inv, l1 * inv, h1 * inv);
        }
    }
}

extern "C" void kernel_launch(void* const* d_in, const int* in_sizes, int n_in,
                              void* d_out, int out_size) {
    const float* x1 = (const float*)d_in[0];
    const float* x2 = (const float*)d_in[1];
    float* out = (float*)d_out;

    const int t2 = CCH * PDW * PDW * (RD2 / 4);
    pad2_kernel<<<(t2 + 255) / 256, 256>>>(x2);

    dim3 grid(336, 27);   // (48 h * 7 s-bands), (9 di * 3 dj-triples)
    corr_kernel<<<grid, 96>>>(x1, out);
}